// round 15
// baseline (speedup 1.0000x reference)
#include <cuda_runtime.h>
#include <cuda_bf16.h>
#include <cstdint>
#include <cstddef>

#define NL 6
#define D 1024
#define H 16
#define FF 4096
#define NB 33
#define DH 64
#define BB 4
#define SS 1024
#define BS (BB*SS)   // 4096

typedef __nv_bfloat16 bf16;

// ---------------- fp32 scratch ----------------
__device__ float g_q[BS*D];
__device__ float g_t[BS*D];
__device__ float g_ffin[BS*D];
__device__ float g_x[BS*D];
__device__ float g_ao[BS*D];                 // attention output fp32
__device__ float g_qE[(size_t)BB*H*SS*NB];

// ---------------- int8 weights (packed [K/2][N][2]) + per-col scales ----------------
__device__ int8_t g_wq8h[NL*D*D], g_wq8l[NL*D*D];
__device__ int8_t g_wk8h[NL*D*D], g_wk8l[NL*D*D];
__device__ int8_t g_wv8h[NL*D*D], g_wv8l[NL*D*D];
__device__ int8_t g_wo8h[NL*D*D], g_wo8l[NL*D*D];
__device__ int8_t g_w18h[(size_t)NL*D*FF], g_w18l[(size_t)NL*D*FF];
__device__ float g_cwq[NL*D], g_cwk[NL*D], g_cwv[NL*D], g_cwo[NL*D];
__device__ float g_cw1[NL*FF];
// W2 stays bf16 split ([K][N] hi/lo)
__device__ bf16 g_w2h[(size_t)NL*FF*D], g_w2l[(size_t)NL*FF*D];

// ---------------- int8 activation planes + row scales ----------------
__device__ int8_t g_x8h[BS*D], g_x8l[BS*D];  __device__ float g_sx[BS];
__device__ int8_t g_a8h[BS*D], g_a8l[BS*D];  __device__ float g_sa[BS];
__device__ int8_t g_f8h[BS*D], g_f8l[BS*D];  __device__ float g_sf[BS];

// ---------------- bf16 planes (attention in, W2 in) ----------------
__device__ bf16 g_qph[BS*D], g_qpl[BS*D];
__device__ bf16 g_kph[BS*D], g_kpl[BS*D];
__device__ bf16 g_vph[BS*D], g_vpl[BS*D];
__device__ bf16 g_hh[(size_t)BS*FF], g_hl[(size_t)BS*FF];

// ---------------- helpers ----------------
__device__ __forceinline__ uint32_t smem_u32(const void* p) {
    return (uint32_t)__cvta_generic_to_shared(p);
}
__device__ __forceinline__ uint32_t pack_hi2(float a, float b) {
    __nv_bfloat162 t = __floats2bfloat162_rn(a, b);
    return *reinterpret_cast<uint32_t*>(&t);
}
__device__ __forceinline__ uint32_t pack_lo2(float a, float b) {
    float ra = a - __bfloat162float(__float2bfloat16(a));
    float rb = b - __bfloat162float(__float2bfloat16(b));
    __nv_bfloat162 t = __floats2bfloat162_rn(ra, rb);
    return *reinterpret_cast<uint32_t*>(&t);
}
__device__ __forceinline__ void cpa16(uint32_t dst_smem, const void* src) {
    asm volatile("cp.async.cg.shared.global [%0], [%1], 16;"
                 :: "r"(dst_smem), "l"(src));
}
__device__ __forceinline__ void ldmx4(uint32_t* r, uint32_t addr) {
    asm volatile("ldmatrix.sync.aligned.m8n8.x4.shared.b16 {%0,%1,%2,%3}, [%4];"
                 : "=r"(r[0]), "=r"(r[1]), "=r"(r[2]), "=r"(r[3]) : "r"(addr));
}
__device__ __forceinline__ void ldmx2t(uint32_t* r, uint32_t addr) {
    asm volatile("ldmatrix.sync.aligned.m8n8.x2.trans.shared.b16 {%0,%1}, [%2];"
                 : "=r"(r[0]), "=r"(r[1]) : "r"(addr));
}
__device__ __forceinline__ void ldmx2(uint32_t* r, uint32_t addr) {
    asm volatile("ldmatrix.sync.aligned.m8n8.x2.shared.b16 {%0,%1}, [%2];"
                 : "=r"(r[0]), "=r"(r[1]) : "r"(addr));
}
__device__ __forceinline__ void mma16816(float* c, const uint32_t* a, const uint32_t* b) {
    asm volatile("mma.sync.aligned.m16n8k16.row.col.f32.bf16.bf16.f32 "
                 "{%0,%1,%2,%3}, {%4,%5,%6,%7}, {%8,%9}, {%0,%1,%2,%3};"
                 : "+f"(c[0]), "+f"(c[1]), "+f"(c[2]), "+f"(c[3])
                 : "r"(a[0]), "r"(a[1]), "r"(a[2]), "r"(a[3]), "r"(b[0]), "r"(b[1]));
}
__device__ __forceinline__ void imma16832(int* c, const uint32_t* a, const uint32_t* b) {
    asm volatile("mma.sync.aligned.m16n8k32.row.col.s32.s8.s8.s32 "
                 "{%0,%1,%2,%3}, {%4,%5,%6,%7}, {%8,%9}, {%0,%1,%2,%3};"
                 : "+r"(c[0]), "+r"(c[1]), "+r"(c[2]), "+r"(c[3])
                 : "r"(a[0]), "r"(a[1]), "r"(a[2]), "r"(a[3]), "r"(b[0]), "r"(b[1]));
}

// ---------------- split fp32 -> bf16 hi/lo planes (W2 weights) ----------------
__global__ __launch_bounds__(256) void split_kernel(
    const float* __restrict__ X, bf16* __restrict__ hi, bf16* __restrict__ lo, int n4)
{
    int i = blockIdx.x * 256 + threadIdx.x;
    if (i < n4) {
        float4 v = ((const float4*)X)[i];
        uint2 h, l;
        h.x = pack_hi2(v.x, v.y); h.y = pack_hi2(v.z, v.w);
        l.x = pack_lo2(v.x, v.y); l.y = pack_lo2(v.z, v.w);
        ((uint2*)hi)[i] = h;
        ((uint2*)lo)[i] = l;
    }
}

// ---------------- weight quant: W[K][N] fp32 -> packed int8 planes [K/2][N][2] + colscale ----------------
__global__ __launch_bounds__(256) void wquant(
    const float* __restrict__ W, int8_t* __restrict__ Qh, int8_t* __restrict__ Ql,
    float* __restrict__ cs, int K, int N)
{
    __shared__ float sm[256];
    __shared__ float sinv[128];
    const float* Wl = W + (size_t)blockIdx.z * K * N;
    int8_t* Qhl = Qh + (size_t)blockIdx.z * K * N;
    int8_t* Qll = Ql + (size_t)blockIdx.z * K * N;
    float* csl = cs + (size_t)blockIdx.z * N;
    int t = threadIdx.x;
    int c = blockIdx.x * 128 + (t & 127);
    float m = 0.f;
    for (int k = (t >> 7); k < K; k += 2)
        m = fmaxf(m, fabsf(Wl[(size_t)k * N + c]));
    sm[t] = m;
    __syncthreads();
    if (t < 128) {
        m = fmaxf(sm[t], sm[t + 128]);
        csl[c] = m * (1.f / 16256.f);
        sinv[t] = (m > 0.f) ? (16256.f / m) : 0.f;
    }
    __syncthreads();
    float inv = sinv[t & 127];
    for (int k2 = (t >> 7); k2 < K / 2; k2 += 2) {
        float v0 = Wl[(size_t)(2 * k2) * N + c];
        float v1 = Wl[(size_t)(2 * k2 + 1) * N + c];
        float q0 = v0 * inv, q1 = v1 * inv;
        int h0 = __float2int_rn(q0 * (1.f / 128.f));
        int l0 = __float2int_rn(q0 - 128.f * h0);
        int h1 = __float2int_rn(q1 * (1.f / 128.f));
        int l1 = __float2int_rn(q1 - 128.f * h1);
        char2 hh; hh.x = (char)h0; hh.y = (char)h1;
        char2 ll; ll.x = (char)l0; ll.y = (char)l1;
        size_t o = ((size_t)k2 * N + c) * 2;
        *(char2*)(Qhl + o) = hh;
        *(char2*)(Qll + o) = ll;
    }
}

// ---------------- row quant: X[M][D] fp32 -> int8 planes [M][D] + rowscale ----------------
__global__ __launch_bounds__(256) void rowquant(
    const float* __restrict__ X, int8_t* __restrict__ Qh, int8_t* __restrict__ Ql,
    float* __restrict__ rs)
{
    __shared__ float sm[8];
    int row = blockIdx.x;
    int t = threadIdx.x;
    float4 v = ((const float4*)(X + (size_t)row * D))[t];
    float m = fmaxf(fmaxf(fabsf(v.x), fabsf(v.y)), fmaxf(fabsf(v.z), fabsf(v.w)));
#pragma unroll
    for (int o = 16; o; o >>= 1) m = fmaxf(m, __shfl_xor_sync(0xffffffffu, m, o));
    if ((t & 31) == 0) sm[t >> 5] = m;
    __syncthreads();
    if (t < 32) {
        m = (t < 8) ? sm[t] : 0.f;
#pragma unroll
        for (int o = 4; o; o >>= 1) m = fmaxf(m, __shfl_xor_sync(0xffffffffu, m, o));
        if (t == 0) sm[0] = m;
    }
    __syncthreads();
    float mx = sm[0];
    float inv = (mx > 0.f) ? (16256.f / mx) : 0.f;
    if (t == 0) rs[row] = mx * (1.f / 16256.f);
    float q0 = v.x * inv, q1 = v.y * inv, q2 = v.z * inv, q3 = v.w * inv;
    int h0 = __float2int_rn(q0 * (1.f / 128.f)), l0 = __float2int_rn(q0 - 128.f * h0);
    int h1 = __float2int_rn(q1 * (1.f / 128.f)), l1 = __float2int_rn(q1 - 128.f * h1);
    int h2 = __float2int_rn(q2 * (1.f / 128.f)), l2 = __float2int_rn(q2 - 128.f * h2);
    int h3 = __float2int_rn(q3 * (1.f / 128.f)), l3 = __float2int_rn(q3 - 128.f * h3);
    char4 hc; hc.x = (char)h0; hc.y = (char)h1; hc.z = (char)h2; hc.w = (char)h3;
    char4 lc; lc.x = (char)l0; lc.y = (char)l1; lc.z = (char)l2; lc.w = (char)l3;
    size_t off = (size_t)row * D + t * 4;
    *(char4*)(Qh + off) = hc;
    *(char4*)(Ql + off) = lc;
}

// ---------------- int8 split GEMM: C = sA_r*sB_c*(16384*hh + 128*cross) + bias (+res)(+relu) ----------------
// A [M][K] int8 2 planes + rowscale; B packed [K/2][N][2] int8 2 planes + colscale.
// Block 128x64, 8 warps (2M x 4N), warp tile 64x16. k-block 64.
#define A8P 80
#define B8P 144
#define A8E (128*A8P)        // 10240
#define B8E (32*B8P)         // 4608
#define ST8 (2*A8E + 2*B8E)  // 29696
#define G8_SMEM (3*ST8)      // 89088
__global__ __launch_bounds__(256, 2) void gemm_i8(
    const int8_t* __restrict__ Ah, const int8_t* __restrict__ Al, const float* __restrict__ Ars,
    const int8_t* Bh0, const int8_t* Bl0, const int8_t* Bh1, const int8_t* Bl1,
    const int8_t* Bh2, const int8_t* Bl2,
    const float* Bcs0, const float* Bcs1, const float* Bcs2,
    const float* bias0, const float* bias1, const float* bias2,
    const float* __restrict__ res,
    float* C0, float* C1, float* C2,
    bf16* Ch0, bf16* Cl0, bf16* Ch1, bf16* Cl1, bf16* Ch2, bf16* Cl2,
    int M, int N, int K, int relu)
{
    extern __shared__ char smem8[];
    const int8_t* Bph = (blockIdx.z == 0) ? Bh0 : (blockIdx.z == 1 ? Bh1 : Bh2);
    const int8_t* Bpl = (blockIdx.z == 0) ? Bl0 : (blockIdx.z == 1 ? Bl1 : Bl2);
    const float* Bcs  = (blockIdx.z == 0) ? Bcs0 : (blockIdx.z == 1 ? Bcs1 : Bcs2);
    const float* bias = (blockIdx.z == 0) ? bias0 : (blockIdx.z == 1 ? bias1 : bias2);
    float* C = (blockIdx.z == 0) ? C0 : (blockIdx.z == 1 ? C1 : C2);
    bf16* Ch = (blockIdx.z == 0) ? Ch0 : (blockIdx.z == 1 ? Ch1 : Ch2);
    bf16* Cl = (blockIdx.z == 0) ? Cl0 : (blockIdx.z == 1 ? Cl1 : Cl2);

    int bm = blockIdx.y * 128, bn = blockIdx.x * 64;
    int tid = threadIdx.x, lane = tid & 31, wid = tid >> 5;
    int wm = (wid >> 2) * 64, wn16 = (wid & 3) * 16;
    int nk = K >> 6;

    int acch[4][2][4], accx[4][2][4];
#pragma unroll
    for (int i = 0; i < 4; i++)
#pragma unroll
        for (int j = 0; j < 2; j++)
#pragma unroll
            for (int t = 0; t < 4; t++) { acch[i][j][t] = 0; accx[i][j][t] = 0; }

    auto load_stage = [&](int kb, int s) {
        char* b = smem8 + s * ST8;
        uint32_t sAh = smem_u32(b), sAl = sAh + A8E;
        uint32_t sBh = sAh + 2 * A8E, sBl = sBh + B8E;
        int k0 = kb << 6;
        int k20 = kb << 5;
#pragma unroll
        for (int u = 0; u < 2; u++) {
            int f = tid + u * 256;           // 0..511
            int r = f >> 2, c4 = f & 3;
            size_t ga = (size_t)(bm + r) * K + k0 + c4 * 16;
            cpa16(sAh + r * A8P + c4 * 16, Ah + ga);
            cpa16(sAl + r * A8P + c4 * 16, Al + ga);
        }
        {
            int k2r = tid >> 3, nb = tid & 7;
            size_t gb = ((size_t)(k20 + k2r) * N + bn) * 2 + nb * 16;
            cpa16(sBh + k2r * B8P + nb * 16, Bph + gb);
            cpa16(sBl + k2r * B8P + nb * 16, Bpl + gb);
        }
        asm volatile("cp.async.commit_group;");
    };

    load_stage(0, 0);
    load_stage(1, 1);

    for (int kb = 0; kb < nk; kb++) {
        if (kb + 1 < nk) {
            asm volatile("cp.async.wait_group 1;");
        } else {
            asm volatile("cp.async.wait_group 0;");
        }
        __syncthreads();
        if (kb + 2 < nk) load_stage(kb + 2, (kb + 2) % 3);

        char* b = smem8 + (kb % 3) * ST8;
        uint32_t sAh = smem_u32(b), sAl = sAh + A8E;
        uint32_t sBh = sAh + 2 * A8E, sBl = sBh + B8E;
#pragma unroll
        for (int ks = 0; ks < 2; ks++) {            // two k32 steps
            uint32_t bhf[2][2], blf[2][2];
            int brow = ks * 16 + (lane & 15);
#pragma unroll
            for (int nj = 0; nj < 2; nj++) {
                ldmx2t(bhf[nj], sBh + brow * B8P + (wn16 + nj * 8) * 2);
                ldmx2t(blf[nj], sBl + brow * B8P + (wn16 + nj * 8) * 2);
            }
#pragma unroll
            for (int mi = 0; mi < 4; mi++) {
                int arow = wm + mi * 16 + (lane & 15);
                int acolb = (ks * 16 + ((lane >> 4) << 3)) * 2;   // b16 idx -> bytes
                uint32_t ahf[4], alf[4];
                ldmx4(ahf, sAh + arow * A8P + acolb);
                ldmx4(alf, sAl + arow * A8P + acolb);
#pragma unroll
                for (int nj = 0; nj < 2; nj++) {
                    imma16832(acch[mi][nj], ahf, bhf[nj]);   // h*h
                    imma16832(accx[mi][nj], ahf, blf[nj]);   // h*l
                    imma16832(accx[mi][nj], alf, bhf[nj]);   // l*h
                }
            }
        }
    }

#pragma unroll
    for (int mi = 0; mi < 4; mi++) {
#pragma unroll
        for (int nj = 0; nj < 2; nj++) {
            int r0 = bm + wm + mi * 16 + (lane >> 2);
            int c0 = bn + wn16 + nj * 8 + (lane & 3) * 2;
            float cs0 = Bcs[c0], cs1 = Bcs[c0 + 1];
            float b0 = bias[c0], b1 = bias[c0 + 1];
#pragma unroll
            for (int half = 0; half < 2; half++) {
                int r = r0 + half * 8;
                float ra = Ars[r];
                float o0 = ra * cs0 * (16384.f * (float)acch[mi][nj][half * 2 + 0]
                                     + 128.f * (float)accx[mi][nj][half * 2 + 0]) + b0;
                float o1 = ra * cs1 * (16384.f * (float)acch[mi][nj][half * 2 + 1]
                                     + 128.f * (float)accx[mi][nj][half * 2 + 1]) + b1;
                if (res) {
                    float2 rr = *(const float2*)(res + (size_t)r * N + c0);
                    o0 += rr.x; o1 += rr.y;
                }
                if (relu) { o0 = fmaxf(o0, 0.f); o1 = fmaxf(o1, 0.f); }
                if (C) { float2 o; o.x = o0; o.y = o1; *(float2*)(C + (size_t)r * N + c0) = o; }
                if (Ch) {
                    *(uint32_t*)(Ch + (size_t)r * N + c0) = pack_hi2(o0, o1);
                    *(uint32_t*)(Cl + (size_t)r * N + c0) = pack_lo2(o0, o1);
                }
            }
        }
    }
}

// ---------------- bf16 split GEMM (W2 only), 3-stage cp.async ----------------
#define APAD 40
#define BPAD 136
#define AE (128*APAD)
#define BE (32*BPAD)
#define STAGE_E (2*AE + 2*BE)
#define GEMM_SMEM (3*STAGE_E*2)
__global__ __launch_bounds__(256, 2) void gemm_bf(
    const bf16* __restrict__ Ah, const bf16* __restrict__ Al,
    const bf16* __restrict__ Bh, const bf16* __restrict__ Bl,
    const float* __restrict__ bias, const float* __restrict__ res,
    float* __restrict__ C, int M, int N, int K)
{
    extern __shared__ bf16 smem[];
    int bm = blockIdx.y * 128, bn = blockIdx.x * 128;
    int tid = threadIdx.x;
    int lane = tid & 31, wid = tid >> 5;
    int wm = (wid >> 2) * 64, wn = (wid & 3) * 32;
    int nk = K >> 5;

    float acc[4][4][4];
#pragma unroll
    for (int i = 0; i < 4; i++)
#pragma unroll
        for (int j = 0; j < 4; j++)
#pragma unroll
            for (int t = 0; t < 4; t++) acc[i][j][t] = 0.f;

    auto load_stage = [&](int kb, int s) {
        bf16* b = smem + s * STAGE_E;
        bf16* sAh = b; bf16* sAl = b + AE; bf16* sBh = b + 2*AE; bf16* sBl = b + 2*AE + BE;
        int k0b = kb << 5;
#pragma unroll
        for (int u = 0; u < 2; u++) {
            int c = tid + u * 256;
            int ar = c >> 2, ac = (c & 3) << 3;
            size_t ga = (size_t)(bm + ar) * K + k0b + ac;
            cpa16(smem_u32(sAh + ar * APAD + ac), Ah + ga);
            cpa16(smem_u32(sAl + ar * APAD + ac), Al + ga);
            int br = c >> 4, bc = (c & 15) << 3;
            size_t gb = (size_t)(k0b + br) * N + bn + bc;
            cpa16(smem_u32(sBh + br * BPAD + bc), Bh + gb);
            cpa16(smem_u32(sBl + br * BPAD + bc), Bl + gb);
        }
        asm volatile("cp.async.commit_group;");
    };

    load_stage(0, 0);
    load_stage(1, 1);

    for (int kb = 0; kb < nk; kb++) {
        if (kb + 1 < nk) {
            asm volatile("cp.async.wait_group 1;");
        } else {
            asm volatile("cp.async.wait_group 0;");
        }
        __syncthreads();
        if (kb + 2 < nk) load_stage(kb + 2, (kb + 2) % 3);

        bf16* b = smem + (kb % 3) * STAGE_E;
        bf16* sAh = b; bf16* sAl = b + AE; bf16* sBh = b + 2*AE; bf16* sBl = b + 2*AE + BE;
#pragma unroll
        for (int h2 = 0; h2 < 2; h2++) {
            int k0 = h2 * 16;
            uint32_t bhf[4][2], blf[4][2];
            int brow = k0 + (lane & 15);
#pragma unroll
            for (int nj = 0; nj < 4; nj++) {
                ldmx2t(bhf[nj], smem_u32(&sBh[brow * BPAD + wn + nj * 8]));
                ldmx2t(blf[nj], smem_u32(&sBl[brow * BPAD + wn + nj * 8]));
            }
#pragma unroll
            for (int mi = 0; mi < 4; mi++) {
                int arow = wm + mi * 16 + (lane & 15);
                int acol = k0 + ((lane >> 4) << 3);
                uint32_t ahf[4], alf[4];
                ldmx4(ahf, smem_u32(&sAh[arow * APAD + acol]));
                ldmx4(alf, smem_u32(&sAl[arow * APAD + acol]));
#pragma unroll
                for (int nj = 0; nj < 4; nj++) {
                    mma16816(acc[mi][nj], ahf, bhf[nj]);
                    mma16816(acc[mi][nj], ahf, blf[nj]);
                    mma16816(acc[mi][nj], alf, bhf[nj]);
                }
            }
        }
    }

#pragma unroll
    for (int mi = 0; mi < 4; mi++) {
#pragma unroll
        for (int nj = 0; nj < 4; nj++) {
            int r0 = bm + wm + mi * 16 + (lane >> 2);
            int c0 = bn + wn + nj * 8 + (lane & 3) * 2;
#pragma unroll
            for (int half = 0; half < 2; half++) {
                int r = r0 + half * 8;
                float o0 = acc[mi][nj][half * 2 + 0] + bias[c0];
                float o1 = acc[mi][nj][half * 2 + 1] + bias[c0 + 1];
                if (res) {
                    float2 rr = *(const float2*)(res + (size_t)r * N + c0);
                    o0 += rr.x; o1 += rr.y;
                }
                float2 o; o.x = o0; o.y = o1;
                *(float2*)(C + (size_t)r * N + c0) = o;
            }
        }
    }
}

// ---------------- qE[b,h,s,nb] = sum_d q[b,s,h*64+d] * Erel[nb,d] ----------------
__global__ __launch_bounds__(256) void qe_kernel(
    const float* __restrict__ Q, const float* __restrict__ Erel, float* __restrict__ qE)
{
    __shared__ float qrow[D];
    __shared__ float er[NB * DH];
    int bs = blockIdx.x;
    int b = bs >> 10, s = bs & 1023;
    for (int i = threadIdx.x; i < D / 4; i += 256)
        ((float4*)qrow)[i] = ((const float4*)(Q + (size_t)bs * D))[i];
    for (int i = threadIdx.x; i < NB * DH / 4; i += 256)
        ((float4*)er)[i] = ((const float4*)Erel)[i];
    __syncthreads();
    for (int idx = threadIdx.x; idx < H * NB; idx += 256) {
        int h = idx / NB, nb = idx % NB;
        float acc = 0.f;
#pragma unroll 16
        for (int d = 0; d < DH; d++) acc += qrow[h * DH + d] * er[nb * DH + d];
        qE[(((size_t)(b * H + h)) * SS + s) * NB + nb] = acc;
    }
}

// ---------------- tensor-core flash attention (split-bf16 mma), fp32 output ----------------
#define AKV0 18432
#define ATT_SMEM 101520
__global__ __launch_bounds__(256, 2) void attn_mma(
    const bf16* __restrict__ qh, const bf16* __restrict__ ql,
    const bf16* __restrict__ kh, const bf16* __restrict__ kl,
    const bf16* __restrict__ vh, const bf16* __restrict__ vl,
    const float* __restrict__ qE, const float* __restrict__ Brel,
    const int* __restrict__ rid,
    float* __restrict__ O)
{
    extern __shared__ char smc[];
    float* sQE = (float*)(smc + 92160);
    float* sBr = (float*)(smc + 100864);
    float* sRed = (float*)(smc + 101008);
    float* sMrg = (float*)(smc + AKV0);
    uint32_t sb = smem_u32(smc);

    int qb = blockIdx.x, h = blockIdx.y, b = blockIdx.z;
    int tid = threadIdx.x, lane = tid & 31, wid = tid >> 5;
    int wq = wid >> 1, wn = wid & 1;
    int qs = wq * 16, ns = wn * 32;
    int q0 = qb * 64;
    int rlo = lane >> 2;

#pragma unroll
    for (int u = 0; u < 4; u++) {
        int f = tid + u * 256;
        int pl = f >> 9;
        int idx = f & 511; int r = idx >> 3, c = idx & 7;
        const bf16* src = pl ? ql : qh;
        uint4 vv = *(const uint4*)(src + ((size_t)(b * SS) + q0 + r) * D + h * DH + c * 8);
        *(uint4*)(smc + pl * 9216 + r * 144 + c * 16) = vv;
    }
    const float* qEb = qE + (((size_t)(b * H + h)) * SS + q0) * NB;
    for (int i = tid; i < 64 * NB; i += 256) {
        int r = i / NB, c = i - r * NB;
        sQE[r * 34 + c] = qEb[r * NB + c];
    }
    for (int i = tid; i < NB; i += 256) sBr[i] = Brel[h * NB + i];

    auto load_kv = [&](int kb) {
        uint32_t base = sb + AKV0 + (kb & 1) * 36864;
        int k0 = kb * 64;
#pragma unroll
        for (int u = 0; u < 8; u++) {
            int f = tid + u * 256;
            int pl = f >> 9;
            int idx = f & 511; int r = idx >> 3, c = idx & 7;
            const bf16* src = (pl == 0) ? kh : (pl == 1) ? kl : (pl == 2) ? vh : vl;
            cpa16(base + pl * 9216 + r * 144 + c * 16,
                  src + ((size_t)(b * SS) + k0 + r) * D + h * DH + c * 8);
        }
        asm volatile("cp.async.commit_group;");
    };

    float m_lo = -1e30f, m_hi = -1e30f, l_lo = 0.f, l_hi = 0.f;
    float oacc[8][4];
#pragma unroll
    for (int j = 0; j < 8; j++)
#pragma unroll
        for (int t = 0; t < 4; t++) oacc[j][t] = 0.f;

    load_kv(0);

    for (int kb = 0; kb < 16; kb++) {
        if (kb + 1 < 16) {
            load_kv(kb + 1);
            asm volatile("cp.async.wait_group 1;");
        } else {
            asm volatile("cp.async.wait_group 0;");
        }
        __syncthreads();
        uint32_t kvb = sb + AKV0 + (kb & 1) * 36864;
        int k0 = kb * 64;

        float sc[4][4];
#pragma unroll
        for (int j = 0; j < 4; j++)
#pragma unroll
            for (int t = 0; t < 4; t++) sc[j][t] = 0.f;
#pragma unroll
        for (int ks = 0; ks < 4; ks++) {
            uint32_t arow = qs + (lane & 15);
            uint32_t acol = (ks * 16 + ((lane >> 4) << 3)) * 2;
            uint32_t aQh[4], aQl[4];
            ldmx4(aQh, sb + arow * 144 + acol);
            ldmx4(aQl, sb + 9216 + arow * 144 + acol);
            int Lr = lane & 15;
            uint32_t bro = (ns + (Lr & 7)) * 144 + (ks * 16 + ((Lr >> 3) << 3)) * 2;
#pragma unroll
            for (int nj = 0; nj < 4; nj++) {
                uint32_t bh_[2], bl_[2];
                ldmx2(bh_, kvb + bro + nj * 8 * 144);
                ldmx2(bl_, kvb + 9216 + bro + nj * 8 * 144);
                mma16816(sc[nj], aQh, bh_);
                mma16816(sc[nj], aQh, bl_);
                mma16816(sc[nj], aQl, bh_);
            }
        }
        int qlo = qs + rlo, qhi = qlo + 8;
#pragma unroll
        for (int nj = 0; nj < 4; nj++) {
            int kkl = ns + nj * 8 + (lane & 3) * 2;
            int2 r1 = *(const int2*)(rid + (size_t)(q0 + qlo) * SS + k0 + kkl);
            int2 r2 = *(const int2*)(rid + (size_t)(q0 + qhi) * SS + k0 + kkl);
            sc[nj][0] = (sc[nj][0] + sQE[qlo * 34 + r1.x] + sBr[r1.x]) * 0.125f;
            sc[nj][1] = (sc[nj][1] + sQE[qlo * 34 + r1.y] + sBr[r1.y]) * 0.125f;
            sc[nj][2] = (sc[nj][2] + sQE[qhi * 34 + r2.x] + sBr[r2.x]) * 0.125f;
            sc[nj][3] = (sc[nj][3] + sQE[qhi * 34 + r2.y] + sBr[r2.y]) * 0.125f;
        }
        float mxlo = fmaxf(fmaxf(sc[0][0], sc[0][1]), fmaxf(sc[1][0], sc[1][1]));
        mxlo = fmaxf(mxlo, fmaxf(fmaxf(sc[2][0], sc[2][1]), fmaxf(sc[3][0], sc[3][1])));
        float mxhi = fmaxf(fmaxf(sc[0][2], sc[0][3]), fmaxf(sc[1][2], sc[1][3]));
        mxhi = fmaxf(mxhi, fmaxf(fmaxf(sc[2][2], sc[2][3]), fmaxf(sc[3][2], sc[3][3])));
#pragma unroll
        for (int o = 1; o < 4; o <<= 1) {
            mxlo = fmaxf(mxlo, __shfl_xor_sync(0xffffffffu, mxlo, o));
            mxhi = fmaxf(mxhi, __shfl_xor_sync(0xffffffffu, mxhi, o));
        }
        if ((lane & 3) == 0) {
            sRed[wn * 64 + qlo] = mxlo;
            sRed[wn * 64 + qhi] = mxhi;
        }
        __syncthreads();
        float tlo = fmaxf(mxlo, sRed[(1 - wn) * 64 + qlo]);
        float thi = fmaxf(mxhi, sRed[(1 - wn) * 64 + qhi]);
        float mn_lo = fmaxf(m_lo, tlo), mn_hi = fmaxf(m_hi, thi);
        float al_lo = __expf(m_lo - mn_lo), al_hi = __expf(m_hi - mn_hi);
        m_lo = mn_lo; m_hi = mn_hi;
        float slo = 0.f, shi = 0.f;
#pragma unroll
        for (int nj = 0; nj < 4; nj++) {
            sc[nj][0] = __expf(sc[nj][0] - mn_lo);
            sc[nj][1] = __expf(sc[nj][1] - mn_lo);
            sc[nj][2] = __expf(sc[nj][2] - mn_hi);
            sc[nj][3] = __expf(sc[nj][3] - mn_hi);
            slo += sc[nj][0] + sc[nj][1];
            shi += sc[nj][2] + sc[nj][3];
        }
#pragma unroll
        for (int o = 1; o < 4; o <<= 1) {
            slo += __shfl_xor_sync(0xffffffffu, slo, o);
            shi += __shfl_xor_sync(0xffffffffu, shi, o);
        }
        l_lo = l_lo * al_lo + slo;
        l_hi = l_hi * al_hi + shi;
#pragma unroll
        for (int j = 0; j < 8; j++) {
            oacc[j][0] *= al_lo; oacc[j][1] *= al_lo;
            oacc[j][2] *= al_hi; oacc[j][3] *= al_hi;
        }
#pragma unroll
        for (int ks2 = 0; ks2 < 2; ks2++) {
            uint32_t aPh[4], aPl[4];
            aPh[0] = pack_hi2(sc[2 * ks2][0], sc[2 * ks2][1]);
            aPh[1] = pack_hi2(sc[2 * ks2][2], sc[2 * ks2][3]);
            aPh[2] = pack_hi2(sc[2 * ks2 + 1][0], sc[2 * ks2 + 1][1]);
            aPh[3] = pack_hi2(sc[2 * ks2 + 1][2], sc[2 * ks2 + 1][3]);
            aPl[0] = pack_lo2(sc[2 * ks2][0], sc[2 * ks2][1]);
            aPl[1] = pack_lo2(sc[2 * ks2][2], sc[2 * ks2][3]);
            aPl[2] = pack_lo2(sc[2 * ks2 + 1][0], sc[2 * ks2 + 1][1]);
            aPl[3] = pack_lo2(sc[2 * ks2 + 1][2], sc[2 * ks2 + 1][3]);
            uint32_t bro = (ns + ks2 * 16 + (lane & 15)) * 144;
#pragma unroll
            for (int njd = 0; njd < 8; njd++) {
                uint32_t bh_[2], bl_[2];
                ldmx2t(bh_, kvb + 18432 + bro + njd * 16);
                ldmx2t(bl_, kvb + 27648 + bro + njd * 16);
                mma16816(oacc[njd], aPh, bh_);
                mma16816(oacc[njd], aPh, bl_);
                mma16816(oacc[njd], aPl, bh_);
            }
        }
        __syncthreads();
    }
    int qlo = qs + rlo, qhi = qlo + 8;
    if (wn == 1) {
#pragma unroll
        for (int njd = 0; njd < 8; njd++) {
            int col = njd * 8 + (lane & 3) * 2;
            float2 a1; a1.x = oacc[njd][0]; a1.y = oacc[njd][1];
            float2 a2; a2.x = oacc[njd][2]; a2.y = oacc[njd][3];
            *(float2*)&sMrg[qlo * 72 + col] = a1;
            *(float2*)&sMrg[qhi * 72 + col] = a2;
        }
        if ((lane & 3) == 0) { sRed[64 + qlo] = l_lo; sRed[64 + qhi] = l_hi; }
    }
    __syncthreads();
    if (wn == 0) {
        float iv_lo = 1.f / (l_lo + sRed[64 + qlo]);
        float iv_hi = 1.f / (l_hi + sRed[64 + qhi]);
        int qglo = q0 + qlo, qghi = q0 + qhi;
#pragma unroll
        for (int njd = 0; njd < 8; njd++) {
            int col = njd * 8 + (lane & 3) * 2;
            float2 x1 = *(float2*)&sMrg[qlo * 72 + col];
            float2 x2 = *(float2*)&sMrg[qhi * 72 + col];
            float2 o1, o2;
            o1.x = (oacc[njd][0] + x1.x) * iv_lo;
            o1.y = (oacc[njd][1] + x1.y) * iv_lo;
            o2.x = (oacc[njd][2] + x2.x) * iv_hi;
            o2.y = (oacc[njd][3] + x2.y) * iv_hi;
            *(float2*)(O + ((size_t)(b * SS) + qglo) * D + h * DH + col) = o1;
            *(float2*)(O + ((size_t)(b * SS) + qghi) * D + h * DH + col) = o2;
        }
    }
}

// ---------------- LayerNorm; fp32 out + optional int8 planes/rowscale ----------------
__global__ __launch_bounds__(256) void ln_kernel(
    const float* __restrict__ X, const float* __restrict__ g,
    const float* __restrict__ be, float* __restrict__ Y,
    int8_t* __restrict__ Qh, int8_t* __restrict__ Ql, float* __restrict__ rs)
{
    __shared__ float ss[8], ssq[8], smx[8];
    int row = blockIdx.x;
    int tid = threadIdx.x;
    const float* x = X + (size_t)row * D;
    float4 v = ((const float4*)x)[tid];
    float s = v.x + v.y + v.z + v.w;
    float sq = v.x * v.x + v.y * v.y + v.z * v.z + v.w * v.w;
#pragma unroll
    for (int o = 16; o; o >>= 1) {
        s += __shfl_xor_sync(0xffffffffu, s, o);
        sq += __shfl_xor_sync(0xffffffffu, sq, o);
    }
    int w = tid >> 5;
    if ((tid & 31) == 0) { ss[w] = s; ssq[w] = sq; }
    __syncthreads();
    if (tid < 32) {
        s = (tid < 8) ? ss[tid] : 0.f;
        sq = (tid < 8) ? ssq[tid] : 0.f;
#pragma unroll
        for (int o = 4; o; o >>= 1) {
            s += __shfl_xor_sync(0xffffffffu, s, o);
            sq += __shfl_xor_sync(0xffffffffu, sq, o);
        }
        if (tid == 0) { ss[0] = s; ssq[0] = sq; }
    }
    __syncthreads();
    float mean = ss[0] * (1.f / D);
    float var = ssq[0] * (1.f / D) - mean * mean;
    float inv = rsqrtf(var + 1e-6f);
    float4 gg = ((const float4*)g)[tid];
    float4 bb = ((const float4*)be)[tid];
    float4 o;
    o.x = (v.x - mean) * inv * gg.x + bb.x;
    o.y = (v.y - mean) * inv * gg.y + bb.y;
    o.z = (v.z - mean) * inv * gg.z + bb.z;
    o.w = (v.w - mean) * inv * gg.w + bb.w;
    ((float4*)(Y + (size_t)row * D))[tid] = o;
    if (Qh) {
        float m = fmaxf(fmaxf(fabsf(o.x), fabsf(o.y)), fmaxf(fabsf(o.z), fabsf(o.w)));
#pragma unroll
        for (int of = 16; of; of >>= 1) m = fmaxf(m, __shfl_xor_sync(0xffffffffu, m, of));
        if ((tid & 31) == 0) smx[w] = m;
        __syncthreads();
        if (tid < 32) {
            m = (tid < 8) ? smx[tid] : 0.f;
#pragma unroll
            for (int of = 4; of; of >>= 1) m = fmaxf(m, __shfl_xor_sync(0xffffffffu, m, of));
            if (tid == 0) smx[0] = m;
        }
        __syncthreads();
        float mx = smx[0];
        float qi = (mx > 0.f) ? (16256.f / mx) : 0.f;
        if (tid == 0) rs[row] = mx * (1.f / 16256.f);
        float q0 = o.x * qi, q1 = o.y * qi, q2 = o.z * qi, q3 = o.w * qi;
        int h0 = __float2int_rn(q0 * (1.f / 128.f)), l0 = __float2int_rn(q0 - 128.f * h0);
        int h1 = __float2int_rn(q1 * (1.f / 128.f)), l1 = __float2int_rn(q1 - 128.f * h1);
        int h2 = __float2int_rn(q2 * (1.f / 128.f)), l2 = __float2int_rn(q2 - 128.f * h2);
        int h3 = __float2int_rn(q3 * (1.f / 128.f)), l3 = __float2int_rn(q3 - 128.f * h3);
        char4 hc; hc.x = (char)h0; hc.y = (char)h1; hc.z = (char)h2; hc.w = (char)h3;
        char4 lc; lc.x = (char)l0; lc.y = (char)l1; lc.z = (char)l2; lc.w = (char)l3;
        size_t off = (size_t)row * D + tid * 4;
        *(char4*)(Qh + off) = hc;
        *(char4*)(Ql + off) = lc;
    }
}

// ---------------- host orchestration ----------------
extern "C" void kernel_launch(void* const* d_in, const int* in_sizes, int n_in,
                              void* d_out, int out_size)
{
    const float* x_in = (const float*)d_in[0];
    const int*   rid  = (const int*)d_in[1];
    const float* Wq = (const float*)d_in[2];
    const float* bq = (const float*)d_in[3];
    const float* Wk = (const float*)d_in[4];
    const float* bk = (const float*)d_in[5];
    const float* Wv = (const float*)d_in[6];
    const float* bv = (const float*)d_in[7];
    const float* Wo = (const float*)d_in[8];
    const float* bo = (const float*)d_in[9];
    const float* Erel = (const float*)d_in[10];
    const float* Brel = (const float*)d_in[11];
    const float* g1  = (const float*)d_in[12];
    const float* be1 = (const float*)d_in[13];
    const float* g2  = (const float*)d_in[14];
    const float* be2 = (const float*)d_in[15];
    const float* W1 = (const float*)d_in[16];
    const float* b1 = (const float*)d_in[17];
    const float* W2 = (const float*)d_in[18];
    const float* b2 = (const float*)d_in[19];

    float *q, *t, *ffin, *xg, *ao, *qe;
    cudaGetSymbolAddress((void**)&q, g_q);
    cudaGetSymbolAddress((void**)&t, g_t);
    cudaGetSymbolAddress((void**)&ffin, g_ffin);
    cudaGetSymbolAddress((void**)&xg, g_x);
    cudaGetSymbolAddress((void**)&ao, g_ao);
    cudaGetSymbolAddress((void**)&qe, g_qE);

    int8_t *wq8h,*wq8l,*wk8h,*wk8l,*wv8h,*wv8l,*wo8h,*wo8l,*w18h,*w18l;
    float *cwq,*cwk,*cwv,*cwo,*cw1;
    int8_t *x8h,*x8l,*a8h,*a8l,*f8h,*f8l;
    float *sx,*sa,*sf;
    bf16 *w2h,*w2l,*qph,*qpl,*kph,*kpl,*vph,*vpl,*hh,*hl;
    cudaGetSymbolAddress((void**)&wq8h, g_wq8h); cudaGetSymbolAddress((void**)&wq8l, g_wq8l);
    cudaGetSymbolAddress((void**)&wk8h, g_wk8h); cudaGetSymbolAddress((void**)&wk8l, g_wk8l);
    cudaGetSymbolAddress((void**)&wv8h, g_wv8h); cudaGetSymbolAddress((void**)&wv8l, g_wv8l);
    cudaGetSymbolAddress((void**)&wo8h, g_wo8h); cudaGetSymbolAddress((void**)&wo8l, g_wo8l);
    cudaGetSymbolAddress((void**)&w18h, g_w18h); cudaGetSymbolAddress((void**)&w18l, g_w18l);
    cudaGetSymbolAddress((void**)&cwq, g_cwq); cudaGetSymbolAddress((void**)&cwk, g_cwk);
    cudaGetSymbolAddress((void**)&cwv, g_cwv); cudaGetSymbolAddress((void**)&cwo, g_cwo);
    cudaGetSymbolAddress((void**)&cw1, g_cw1);
    cudaGetSymbolAddress((void**)&x8h, g_x8h); cudaGetSymbolAddress((void**)&x8l, g_x8l);
    cudaGetSymbolAddress((void**)&a8h, g_a8h); cudaGetSymbolAddress((void**)&a8l, g_a8l);
    cudaGetSymbolAddress((void**)&f8h, g_f8h); cudaGetSymbolAddress((void**)&f8l, g_f8l);
    cudaGetSymbolAddress((void**)&sx, g_sx); cudaGetSymbolAddress((void**)&sa, g_sa);
    cudaGetSymbolAddress((void**)&sf, g_sf);
    cudaGetSymbolAddress((void**)&w2h, g_w2h); cudaGetSymbolAddress((void**)&w2l, g_w2l);
    cudaGetSymbolAddress((void**)&qph, g_qph); cudaGetSymbolAddress((void**)&qpl, g_qpl);
    cudaGetSymbolAddress((void**)&kph, g_kph); cudaGetSymbolAddress((void**)&kpl, g_kpl);
    cudaGetSymbolAddress((void**)&vph, g_vph); cudaGetSymbolAddress((void**)&vpl, g_vpl);
    cudaGetSymbolAddress((void**)&hh, g_hh);   cudaGetSymbolAddress((void**)&hl, g_hl);

    cudaFuncSetAttribute(gemm_i8, cudaFuncAttributeMaxDynamicSharedMemorySize, G8_SMEM);
    cudaFuncSetAttribute(gemm_bf, cudaFuncAttributeMaxDynamicSharedMemorySize, GEMM_SMEM);
    cudaFuncSetAttribute(attn_mma, cudaFuncAttributeMaxDynamicSharedMemorySize, ATT_SMEM);

    // ---- pre-pass: quantize weights, split W2 to bf16, quantize layer-0 input ----
    wquant<<<dim3(8, 1, NL), 256>>>(Wq, wq8h, wq8l, cwq, D, D);
    wquant<<<dim3(8, 1, NL), 256>>>(Wk, wk8h, wk8l, cwk, D, D);
    wquant<<<dim3(8, 1, NL), 256>>>(Wv, wv8h, wv8l, cwv, D, D);
    wquant<<<dim3(8, 1, NL), 256>>>(Wo, wo8h, wo8l, cwo, D, D);
    wquant<<<dim3(32, 1, NL), 256>>>(W1, w18h, w18l, cw1, D, FF);
    {
        int nDF = (int)((size_t)NL * FF * D / 4);
        split_kernel<<<(nDF + 255) / 256, 256>>>(W2, w2h, w2l, nDF);
    }
    rowquant<<<BS, 256>>>(x_in, x8h, x8l, sx);

    const float* Xf = x_in;
    for (int l = 0; l < NL; l++) {
        const size_t wDD = (size_t)l * D * D;
        const size_t wDF = (size_t)l * D * FF;
        // fused QKV (int8): q -> fp32 + bf16 planes; k,v -> bf16 planes
        gemm_i8<<<dim3(16, 32, 3), 256, G8_SMEM>>>(x8h, x8l, sx,
            wq8h + wDD, wq8l + wDD, wk8h + wDD, wk8l + wDD, wv8h + wDD, wv8l + wDD,
            cwq + l * D, cwk + l * D, cwv + l * D,
            bq + l * D, bk + l * D, bv + l * D, nullptr,
            q, nullptr, nullptr,
            qph, qpl, kph, kpl, vph, vpl, BS, D, D, 0);
        qe_kernel<<<BS, 256>>>(q, Erel + (size_t)l * NB * DH, qe);
        attn_mma<<<dim3(16, 16, 4), 256, ATT_SMEM>>>(qph, qpl, kph, kpl, vph, vpl,
            qe, Brel + (size_t)l * H * NB, rid, ao);
        rowquant<<<BS, 256>>>(ao, a8h, a8l, sa);
        // Wo (int8) + residual
        gemm_i8<<<dim3(16, 32, 1), 256, G8_SMEM>>>(a8h, a8l, sa,
            wo8h + wDD, wo8l + wDD, nullptr, nullptr, nullptr, nullptr,
            cwo + l * D, nullptr, nullptr,
            bo + l * D, nullptr, nullptr, Xf,
            t, nullptr, nullptr,
            nullptr, nullptr, nullptr, nullptr, nullptr, nullptr, BS, D, D, 0);
        ln_kernel<<<BS, 256>>>(t, g1 + l * D, be1 + l * D, ffin, f8h, f8l, sf);
        // W1 (int8) + relu -> bf16 planes for W2
        gemm_i8<<<dim3(64, 32, 1), 256, G8_SMEM>>>(f8h, f8l, sf,
            w18h + wDF, w18l + wDF, nullptr, nullptr, nullptr, nullptr,
            cw1 + (size_t)l * FF, nullptr, nullptr,
            b1 + (size_t)l * FF, nullptr, nullptr, nullptr,
            nullptr, nullptr, nullptr,
            hh, hl, nullptr, nullptr, nullptr, nullptr, BS, FF, D, 1);
        // W2 (bf16 3-term) + residual
        gemm_bf<<<dim3(8, 32, 1), 256, GEMM_SMEM>>>(hh, hl,
            w2h + wDF, w2l + wDF, b2 + l * D, ffin, t, BS, D, FF);
        float* out = (l == NL - 1) ? (float*)d_out : xg;
        int8_t* oq_h = (l == NL - 1) ? nullptr : x8h;
        int8_t* oq_l = (l == NL - 1) ? nullptr : x8l;
        ln_kernel<<<BS, 256>>>(t, g2 + l * D, be2 + l * D, out, oq_h, oq_l, sx);
        Xf = xg;
    }
}